// round 1
// baseline (speedup 1.0000x reference)
#include <cuda_runtime.h>

// Problem constants
#define BATCH  4
#define C_IN   256
#define C_OUT  256
#define HH     64
#define WW     64
#define HW     4096      // 64*64
#define KTAPS  9
#define KTOT   (C_IN * KTAPS)   // 2304 (tap-major reordered)
#define MTOT   (BATCH * HW)     // 16384

// GEMM tiling
#define BM 128
#define BN 64
#define BK 32

// Weight transposed to [kord][o], kord = tap*256 + c  (2.25 MB scratch)
__device__ float g_wT[KTAPS * C_IN * C_OUT];

// w: [O][C][3][3] -> g_wT[(tap*256+c)*256 + o]
__global__ void transpose_w_kernel(const float* __restrict__ w) {
    int i = blockIdx.x * 256 + threadIdx.x;   // i = kord*256 + o
    int o    = i & 255;
    int kord = i >> 8;
    int tap  = kord >> 8;   // 0..8
    int c    = kord & 255;
    g_wT[i] = w[o * (C_IN * KTAPS) + c * KTAPS + tap];
}

__global__ __launch_bounds__(256)
void dconv_kernel(const float* __restrict__ x,
                  const float* __restrict__ off,
                  const float* __restrict__ bias,
                  float* __restrict__ out)
{
    __shared__ float As[BK][BM];        // 16 KB
    __shared__ float Bs[BK][BN];        // 8 KB
    __shared__ float Cs[32][BM + 1];    // ~16.5 KB, epilogue transpose

    const int tid   = threadIdx.x;
    const int mtile = blockIdx.x * BM;
    const int ntile = blockIdx.y * BN;

    // ---- A-fill role: each thread owns one position m = tid & 127 ----
    const int am = tid & (BM - 1);
    const int p  = mtile + am;
    const int b  = p >> 12;          // / 4096
    const int hw = p & 4095;
    const int ho = hw >> 6;
    const int wo = hw & 63;
    const float* xb = x + (b << 20); // b * C_IN * HW
    const int kk0 = tid >> 7;        // 0 or 1

    // ---- compute role ----
    const int ty = tid >> 4, tx = tid & 15;
    const int m0 = ty * 8, n0 = tx * 4;

    float acc[8][4];
    #pragma unroll
    for (int mi = 0; mi < 8; ++mi)
        #pragma unroll
        for (int j = 0; j < 4; ++j) acc[mi][j] = 0.0f;

    for (int tap = 0; tap < KTAPS; ++tap) {
        // --- bilinear sampling params for (position am, tap): registers only ---
        const float offy = off[((b * 18 + 2 * tap)     << 12) + hw];
        const float offx = off[((b * 18 + 2 * tap + 1) << 12) + hw];
        const float py = (float)(ho - 1 + tap / 3) + offy;
        const float px = (float)(wo - 1 + tap % 3) + offx;
        const float y0f = floorf(py), x0f = floorf(px);
        const int y0 = (int)y0f, x0 = (int)x0f;
        const int y1 = y0 + 1,  x1 = x0 + 1;
        const float fy = py - y0f, fx = px - x0f;
        const float gy = 1.0f - fy, gx = 1.0f - fx;
        float w00 = gy * gx, w01 = gy * fx, w10 = fy * gx, w11 = fy * fx;
        const bool vy0 = (unsigned)y0 < 64u, vy1 = (unsigned)y1 < 64u;
        const bool vx0 = (unsigned)x0 < 64u, vx1 = (unsigned)x1 < 64u;
        if (!(vy0 && vx0)) w00 = 0.0f;
        if (!(vy0 && vx1)) w01 = 0.0f;
        if (!(vy1 && vx0)) w10 = 0.0f;
        if (!(vy1 && vx1)) w11 = 0.0f;
        const int cy0 = min(max(y0, 0), 63), cy1 = min(max(y1, 0), 63);
        const int cx0 = min(max(x0, 0), 63), cx1 = min(max(x1, 0), 63);
        const int i00 = cy0 * 64 + cx0, i01 = cy0 * 64 + cx1;
        const int i10 = cy1 * 64 + cx0, i11 = cy1 * 64 + cx1;

        for (int cb = 0; cb < C_IN / BK; ++cb) {   // 8 chunks of 32 channels
            const int kb = cb * BK;
            __syncthreads();

            // Fill As[kk][m]: this thread handles m=am, kk = kk0 + 2*it.
            // Consecutive lanes -> consecutive m -> spatially local gathers.
            #pragma unroll
            for (int it = 0; it < 16; ++it) {
                const int kkv = kk0 + 2 * it;
                const float* xc = xb + ((kb + kkv) << 12);
                float v = w00 * __ldg(xc + i00) + w01 * __ldg(xc + i01)
                        + w10 * __ldg(xc + i10) + w11 * __ldg(xc + i11);
                As[kkv][am] = v;
            }
            // Fill Bs[kk][n] from g_wT (row-major over o) — fully coalesced.
            #pragma unroll
            for (int it = 0; it < 8; ++it) {
                const int e = tid + it * 256;
                const int n = e & 63, kkb = e >> 6;
                Bs[kkb][n] = g_wT[(tap * 256 + kb + kkb) * 256 + ntile + n];
            }
            __syncthreads();

            // 8x4 register tile mainloop
            #pragma unroll
            for (int k = 0; k < BK; ++k) {
                const float4 a0 = *(const float4*)&As[k][m0];
                const float4 a1 = *(const float4*)&As[k][m0 + 4];
                const float4 bq = *(const float4*)&Bs[k][n0];
                const float av[8] = {a0.x, a0.y, a0.z, a0.w,
                                     a1.x, a1.y, a1.z, a1.w};
                const float bv[4] = {bq.x, bq.y, bq.z, bq.w};
                #pragma unroll
                for (int mi = 0; mi < 8; ++mi)
                    #pragma unroll
                    for (int j = 0; j < 4; ++j)
                        acc[mi][j] = fmaf(av[mi], bv[j], acc[mi][j]);
            }
        }
    }

    // ---- Epilogue: transpose through smem for coalesced [B,O,H,W] stores ----
    #pragma unroll
    for (int half = 0; half < 2; ++half) {
        __syncthreads();
        if ((n0 >> 5) == half) {
            #pragma unroll
            for (int j = 0; j < 4; ++j) {
                const int n = (n0 + j) & 31;
                #pragma unroll
                for (int mi = 0; mi < 8; ++mi)
                    Cs[n][m0 + mi] = acc[mi][j];
            }
        }
        __syncthreads();
        #pragma unroll
        for (int it = 0; it < 16; ++it) {
            const int e = tid + it * 256;
            const int m = e & 127;
            const int n = e >> 7;                 // 0..31
            const int nglob = ntile + half * 32 + n;
            const int pg = mtile + m;
            const int bb = pg >> 12, hw2 = pg & 4095;
            out[(bb << 20) + (nglob << 12) + hw2] = Cs[n][m] + bias[nglob];
        }
    }
}

extern "C" void kernel_launch(void* const* d_in, const int* in_sizes, int n_in,
                              void* d_out, int out_size)
{
    const float* x    = (const float*)d_in[0];
    const float* off  = (const float*)d_in[1];
    const float* w    = (const float*)d_in[2];
    const float* bias = (const float*)d_in[3];
    float* out        = (float*)d_out;

    transpose_w_kernel<<<(KTAPS * C_IN * C_OUT) / 256, 256>>>(w);

    dim3 grid(MTOT / BM, C_OUT / BN);   // 128 x 4 = 512 blocks
    dconv_kernel<<<grid, 256>>>(x, off, bias, out);
}

// round 3
// speedup vs baseline: 1.5196x; 1.5196x over previous
#include <cuda_runtime.h>
#include <cuda_bf16.h>
#include <cstdint>

// ---------------- problem constants ----------------
#define C_IN   256
#define C_OUT  256
#define HW     4096
#define KTAPS  9
#define KTOT   2304          // tap-major: kord = tap*256 + c
#define MTOT   16384

// ---------------- GEMM tiling ----------------
#define BM 128
#define BN 256
#define BK 64
#define NCHUNK 36            // KTOT/BK

#define PITCH  144           // 64 ch * 2B + 16B pad  (conflict-free)
#define ABUF   (BM * PITCH)  // 18432
#define BBUF   (BN * PITCH)  // 36864

#define AH_OFF    0
#define AL_OFF    36864
#define BH_OFF    73728
#define BL_OFF    147456
#define PARAM_OFF 221184     // 128 * 32B = 4KB
#define SMEM_TOTAL 225280

#define CS_PITCH 129

// ---------------- device scratch ----------------
__device__ float    g_xT[4 * HW * C_IN];                 // NHWC, 16MB
__device__ __align__(16) uint16_t g_wBh[C_OUT * KTOT];   // bf16 hi, [o][kord]
__device__ __align__(16) uint16_t g_wBl[C_OUT * KTOT];   // bf16 lo

// ---------------- prep kernels ----------------
__global__ void prep_w(const float* __restrict__ w) {
    int i = blockIdx.x * 256 + threadIdx.x;      // over C_OUT*KTOT
    int kord = i % KTOT;
    int o    = i / KTOT;
    int tap  = kord >> 8;
    int c    = kord & 255;
    float v = w[o * KTOT + c * KTAPS + tap];
    __nv_bfloat16 h = __float2bfloat16_rn(v);
    float r = v - __bfloat162float(h);
    __nv_bfloat16 l = __float2bfloat16_rn(r);
    g_wBh[i] = *(uint16_t*)&h;
    g_wBl[i] = *(uint16_t*)&l;
}

__global__ void transpose_x(const float* __restrict__ x) {
    __shared__ float t[32][33];
    const int b   = blockIdx.z;
    const int hw0 = blockIdx.x * 32;
    const int c0  = blockIdx.y * 32;
    const int tx  = threadIdx.x, ty = threadIdx.y;
    #pragma unroll
    for (int i = 0; i < 4; ++i)
        t[ty + i * 8][tx] = x[((b * C_IN + c0 + ty + i * 8) << 12) + hw0 + tx];
    __syncthreads();
    #pragma unroll
    for (int i = 0; i < 4; ++i)
        g_xT[b * (HW * C_IN) + (hw0 + ty + i * 8) * C_IN + c0 + tx] =
            t[tx][ty + i * 8];
}

// ---------------- asm helpers ----------------
__device__ __forceinline__ uint32_t smem_u32(const void* p) {
    uint32_t a;
    asm("{ .reg .u64 t; cvta.to.shared.u64 t, %1; cvt.u32.u64 %0, t; }"
        : "=r"(a) : "l"(p));
    return a;
}

__device__ __forceinline__ void ldsm4(uint32_t* r, uint32_t a) {
    asm volatile("ldmatrix.sync.aligned.m8n8.x4.shared.b16 {%0,%1,%2,%3}, [%4];"
                 : "=r"(r[0]), "=r"(r[1]), "=r"(r[2]), "=r"(r[3]) : "r"(a));
}
__device__ __forceinline__ void ldsm2(uint32_t* r, uint32_t a) {
    asm volatile("ldmatrix.sync.aligned.m8n8.x2.shared.b16 {%0,%1}, [%2];"
                 : "=r"(r[0]), "=r"(r[1]) : "r"(a));
}
__device__ __forceinline__ void hmma(float* d, const uint32_t* a, const uint32_t* b) {
    asm volatile(
        "mma.sync.aligned.m16n8k16.row.col.f32.bf16.bf16.f32 "
        "{%0,%1,%2,%3}, {%4,%5,%6,%7}, {%8,%9}, {%0,%1,%2,%3};"
        : "+f"(d[0]), "+f"(d[1]), "+f"(d[2]), "+f"(d[3])
        : "r"(a[0]), "r"(a[1]), "r"(a[2]), "r"(a[3]), "r"(b[0]), "r"(b[1]));
}

// ---------------- main kernel ----------------
__global__ __launch_bounds__(256, 1)
void dconv_mma(const float* __restrict__ off,
               const float* __restrict__ bias,
               float* __restrict__ out)
{
    extern __shared__ char smem[];
    const uint32_t sbase = smem_u32(smem);
    const int tid = threadIdx.x;
    const int wid = tid >> 5;
    const int lid = tid & 31;

    const int b   = blockIdx.x >> 5;           // image
    const int hw0 = (blockIdx.x & 31) << 7;    // first position of tile
    const char* xTb = (const char*)g_xT + ((size_t)b << 22);   // 4MB per image

    // warp tile
    const int mrow = (wid & 1) * 64;
    const int ncol = (wid >> 1) * 64;
    const uint32_t aoff = (uint32_t)(lid & 15) * PITCH + (uint32_t)(lid >> 4) * 16;
    const uint32_t boff = (uint32_t)(lid & 7) * PITCH + (uint32_t)((lid >> 3) & 1) * 16;

    float acc[4][8][4];
    #pragma unroll
    for (int i = 0; i < 4; ++i)
        #pragma unroll
        for (int j = 0; j < 8; ++j)
            #pragma unroll
            for (int k = 0; k < 4; ++k) acc[i][j][k] = 0.f;

    // ---- lambdas ----
    auto param_fill = [&](int tap) {
        if (tid < 128) {
            const int pos = tid;
            const int hw  = hw0 + pos;
            const int ho  = hw >> 6, wo = hw & 63;
            const float offy = off[((b * 18 + 2 * tap)     << 12) + hw];
            const float offx = off[((b * 18 + 2 * tap + 1) << 12) + hw];
            const float py = (float)(ho - 1 + tap / 3) + offy;
            const float px = (float)(wo - 1 + tap % 3) + offx;
            const float y0f = floorf(py), x0f = floorf(px);
            const int y0 = (int)y0f, x0 = (int)x0f;
            const float fy = py - y0f, fx = px - x0f;
            float w00 = (1.f - fy) * (1.f - fx), w01 = (1.f - fy) * fx;
            float w10 = fy * (1.f - fx),         w11 = fy * fx;
            const bool vy0 = (unsigned)y0 < 64u, vy1 = (unsigned)(y0 + 1) < 64u;
            const bool vx0 = (unsigned)x0 < 64u, vx1 = (unsigned)(x0 + 1) < 64u;
            if (!(vy0 && vx0)) w00 = 0.f;
            if (!(vy0 && vx1)) w01 = 0.f;
            if (!(vy1 && vx0)) w10 = 0.f;
            if (!(vy1 && vx1)) w11 = 0.f;
            const int cy0 = min(max(y0, 0), 63), cy1 = min(max(y0 + 1, 0), 63);
            const int cx0 = min(max(x0, 0), 63), cx1 = min(max(x0 + 1, 0), 63);
            // byte offsets into NHWC image (idx * 256 ch * 4B = idx<<10)
            const int o00 = (cy0 * 64 + cx0) << 10, o01 = (cy0 * 64 + cx1) << 10;
            const int o10 = (cy1 * 64 + cx0) << 10, o11 = (cy1 * 64 + cx1) << 10;
            char* pp = smem + PARAM_OFF + pos * 32;
            *(float4*)pp        = make_float4(w00, w01, w10, w11);
            *(int4*)(pp + 16)   = make_int4(o00, o01, o10, o11);
        }
    };

    auto fill = [&](int chunk) {
        const int buf = chunk & 1;
        // ---- B fill: [n][k] rows, 64 ch, hi+lo ----
        {
            char* bh = smem + BH_OFF + buf * BBUF;
            char* bl = smem + BL_OFF + buf * BBUF;
            const int ke = chunk * 64;
            #pragma unroll
            for (int i = 0; i < 8; ++i) {
                const int id = tid + (i << 8);
                const int n = id >> 3, s = id & 7;
                const int dsto = n * PITCH + s * 16;
                *(uint4*)(bh + dsto) = *(const uint4*)(g_wBh + n * KTOT + ke + s * 8);
                *(uint4*)(bl + dsto) = *(const uint4*)(g_wBl + n * KTOT + ke + s * 8);
            }
        }
        // ---- A fill: bilinear gather from NHWC ----
        {
            char* ah = smem + AH_OFF + buf * ABUF;
            char* al = smem + AL_OFF + buf * ABUF;
            const int chbase4 = ((chunk & 3) << 6) * 4;   // byte offset of chunk's 64 ch
            const int psub = lid >> 3;
            const int q    = lid & 7;
            #pragma unroll
            for (int it = 0; it < 4; ++it) {
                const int pos = (wid << 4) + (it << 2) + psub;
                const char* pp = smem + PARAM_OFF + pos * 32;
                const float4 wv = *(const float4*)pp;
                const int4  ov = *(const int4*)(pp + 16);
                const char* src = xTb + chbase4 + q * 16;
                #pragma unroll
                for (int hh = 0; hh < 2; ++hh) {
                    const int co = hh * 128;
                    const float4 a0 = *(const float4*)(src + ov.x + co);
                    const float4 a1 = *(const float4*)(src + ov.y + co);
                    const float4 a2 = *(const float4*)(src + ov.z + co);
                    const float4 a3 = *(const float4*)(src + ov.w + co);
                    float4 v;
                    v.x = wv.x*a0.x + wv.y*a1.x + wv.z*a2.x + wv.w*a3.x;
                    v.y = wv.x*a0.y + wv.y*a1.y + wv.z*a2.y + wv.w*a3.y;
                    v.z = wv.x*a0.z + wv.y*a1.z + wv.z*a2.z + wv.w*a3.z;
                    v.w = wv.x*a0.w + wv.y*a1.w + wv.z*a2.w + wv.w*a3.w;
                    __nv_bfloat162 h0 = __floats2bfloat162_rn(v.x, v.y);
                    __nv_bfloat162 h1 = __floats2bfloat162_rn(v.z, v.w);
                    __nv_bfloat162 l0 = __floats2bfloat162_rn(
                        v.x - __bfloat162float(h0.x), v.y - __bfloat162float(h0.y));
                    __nv_bfloat162 l1 = __floats2bfloat162_rn(
                        v.z - __bfloat162float(h1.x), v.w - __bfloat162float(h1.y));
                    const int dsto = pos * PITCH + hh * 64 + q * 8;
                    *(uint2*)(ah + dsto) = make_uint2(*(uint32_t*)&h0, *(uint32_t*)&h1);
                    *(uint2*)(al + dsto) = make_uint2(*(uint32_t*)&l0, *(uint32_t*)&l1);
                }
            }
        }
    };

    auto do_mma = [&](int buf) {
        const uint32_t sAh = sbase + AH_OFF + buf * ABUF + mrow * PITCH + aoff;
        const uint32_t sAl = sbase + AL_OFF + buf * ABUF + mrow * PITCH + aoff;
        const uint32_t sBh = sbase + BH_OFF + buf * BBUF + ncol * PITCH + boff;
        const uint32_t sBl = sbase + BL_OFF + buf * BBUF + ncol * PITCH + boff;
        #pragma unroll
        for (int ks = 0; ks < 4; ++ks) {
            const uint32_t ka = ks * 32;
            uint32_t ahf[4][4], alf[4][4];
            #pragma unroll
            for (int ms = 0; ms < 4; ++ms) {
                ldsm4(ahf[ms], sAh + ms * (16 * PITCH) + ka);
                ldsm4(alf[ms], sAl + ms * (16 * PITCH) + ka);
            }
            #pragma unroll
            for (int ns = 0; ns < 8; ++ns) {
                uint32_t bhf[2], blf[2];
                ldsm2(bhf, sBh + ns * (8 * PITCH) + ka);
                ldsm2(blf, sBl + ns * (8 * PITCH) + ka);
                #pragma unroll
                for (int ms = 0; ms < 4; ++ms) {
                    hmma(acc[ms][ns], ahf[ms], bhf);
                    hmma(acc[ms][ns], ahf[ms], blf);
                    hmma(acc[ms][ns], alf[ms], bhf);
                }
            }
        }
    };

    // ---- pipeline ----
    param_fill(0);
    __syncthreads();
    fill(0);
    __syncthreads();
    #pragma unroll 1
    for (int chunk = 0; chunk < NCHUNK; ++chunk) {
        const int nxt = chunk + 1;
        if (nxt < NCHUNK) {
            if ((nxt & 3) == 0) {
                param_fill(nxt >> 2);
                __syncthreads();
            }
            fill(nxt);
        }
        do_mma(chunk & 1);
        __syncthreads();
    }

    // ---- epilogue: transpose through smem, coalesced stores ----
    float* csf = (float*)smem;
    const int g = lid >> 2;
    const int t2 = (lid & 3) * 2;
    #pragma unroll 1
    for (int p = 0; p < 8; ++p) {
        if ((wid >> 1) == (p >> 1)) {
            const int nsb = (p & 1) * 4;
            #pragma unroll
            for (int ns2 = 0; ns2 < 4; ++ns2) {
                const int nl = ns2 * 8 + t2;
                #pragma unroll
                for (int ms = 0; ms < 4; ++ms) {
                    const float* a4 = acc[ms][nsb + ns2];
                    const int m = mrow + ms * 16 + g;
                    csf[nl * CS_PITCH + m]           = a4[0];
                    csf[(nl + 1) * CS_PITCH + m]     = a4[1];
                    csf[nl * CS_PITCH + m + 8]       = a4[2];
                    csf[(nl + 1) * CS_PITCH + m + 8] = a4[3];
                }
            }
        }
        __syncthreads();
        const int outbase = (b << 20) + hw0;
        #pragma unroll
        for (int it = 0; it < 16; ++it) {
            const int e = tid + it * 256;
            const int mm = e & 127;
            const int nn = e >> 7;
            const int n = p * 32 + nn;
            out[outbase + (n << 12) + mm] = csf[nn * CS_PITCH + mm] + __ldg(bias + n);
        }
        __syncthreads();
    }
}

extern "C" void kernel_launch(void* const* d_in, const int* in_sizes, int n_in,
                              void* d_out, int out_size)
{
    const float* x    = (const float*)d_in[0];
    const float* off  = (const float*)d_in[1];
    const float* w    = (const float*)d_in[2];
    const float* bias = (const float*)d_in[3];
    float* out        = (float*)d_out;

    cudaFuncSetAttribute(dconv_mma, cudaFuncAttributeMaxDynamicSharedMemorySize,
                         SMEM_TOTAL);

    transpose_x<<<dim3(HW / 32, C_IN / 32, 4), dim3(32, 8)>>>(x);
    prep_w<<<(C_OUT * KTOT) / 256, 256>>>(w);
    dconv_mma<<<MTOT / BM, 256, SMEM_TOTAL>>>(off, bias, out);
}